// round 3
// baseline (speedup 1.0000x reference)
#include <cuda_runtime.h>

// Shapes (fixed): B=8, L=256, F=512, U=512.
#define Bn 8
#define Ln 256
#define Fn 512
#define Un 512
#define Mn (Bn*Ln)   // 2048

// Scratch
__device__ __align__(16) float g_Q[Mn * Un];           // [2048][512]
__device__ __align__(16) float g_KT[Bn * Un * Ln];     // [8][512][256]  K+bh, u-major
__device__ __align__(16) float g_E[2 * Bn * Ln * Ln];  // [2][8][256][256] partial scores

__device__ __forceinline__ float tanh_approx(float x) {
    float y;
    asm("tanh.approx.f32 %0, %1;" : "=f"(y) : "f"(x));
    return y;
}

// ---------------------------------------------------------------------------
// Kernel 1: dual SGEMM, Q = X*Wq and KT = (X*Wk + bh)^T.
// 64x64 tile, BK=16, 128 threads, 8x4 microtile, double-buffered smem.
// ---------------------------------------------------------------------------
#define PBM 64
#define PBN 64
#define PBK 16
#define PNK (Fn/PBK)   // 32

__global__ __launch_bounds__(128) void proj_kernel(
    const float* __restrict__ X,    // [2048,512]
    const float* __restrict__ Wq,   // [512,512]
    const float* __restrict__ Wk,   // [512,512]
    const float* __restrict__ bh)   // [512]
{
    __shared__ float As [2][PBK][PBM];
    __shared__ float B1s[2][PBK][PBN];
    __shared__ float B2s[2][PBK][PBN];

    const int tid = threadIdx.x;
    const int m0 = blockIdx.y * PBM;
    const int n0 = blockIdx.x * PBN;

    // loaders
    const int a_row = tid >> 1;          // 0..63
    const int a_k   = (tid & 1) * 8;     // 0 or 8
    const int b_row = tid >> 3;          // 0..15
    const int b_n   = (tid & 7) * 8;     // 0,8,...,56

    // compute mapping: ty owns 8 m-rows, tx owns 4 n-cols
    const int ty = tid >> 4;             // 0..7
    const int tx = tid & 15;             // 0..15

    float4 acc1[8], acc2[8];             // [m-sub] x (4 n) each
#pragma unroll
    for (int i = 0; i < 8; i++) {
        acc1[i] = make_float4(0.f,0.f,0.f,0.f);
        acc2[i] = make_float4(0.f,0.f,0.f,0.f);
    }

    float4 av0, av1, bq0, bq1, bk0, bk1;

#define PLOAD(K0)                                                             \
    do {                                                                      \
        av0 = *(const float4*)&X [(m0 + a_row) * Fn + (K0) + a_k];            \
        av1 = *(const float4*)&X [(m0 + a_row) * Fn + (K0) + a_k + 4];        \
        bq0 = *(const float4*)&Wq[((K0) + b_row) * Un + n0 + b_n];            \
        bq1 = *(const float4*)&Wq[((K0) + b_row) * Un + n0 + b_n + 4];        \
        bk0 = *(const float4*)&Wk[((K0) + b_row) * Un + n0 + b_n];            \
        bk1 = *(const float4*)&Wk[((K0) + b_row) * Un + n0 + b_n + 4];        \
    } while (0)

#define PSTORE(S)                                                             \
    do {                                                                      \
        As[S][a_k+0][a_row] = av0.x; As[S][a_k+1][a_row] = av0.y;             \
        As[S][a_k+2][a_row] = av0.z; As[S][a_k+3][a_row] = av0.w;             \
        As[S][a_k+4][a_row] = av1.x; As[S][a_k+5][a_row] = av1.y;             \
        As[S][a_k+6][a_row] = av1.z; As[S][a_k+7][a_row] = av1.w;             \
        *(float4*)&B1s[S][b_row][b_n]     = bq0;                              \
        *(float4*)&B1s[S][b_row][b_n + 4] = bq1;                              \
        *(float4*)&B2s[S][b_row][b_n]     = bk0;                              \
        *(float4*)&B2s[S][b_row][b_n + 4] = bk1;                              \
    } while (0)

    PLOAD(0);
    PSTORE(0);
    __syncthreads();

    for (int k0 = 0; k0 < PNK; k0++) {
        const int s = k0 & 1;
        if (k0 + 1 < PNK) PLOAD((k0 + 1) * PBK);
#pragma unroll
        for (int kk = 0; kk < PBK; kk++) {
            float4 a0 = *(const float4*)&As[s][kk][ty * 8];
            float4 a1 = *(const float4*)&As[s][kk][ty * 8 + 4];
            float4 c  = *(const float4*)&B1s[s][kk][tx * 4];
            float4 d  = *(const float4*)&B2s[s][kk][tx * 4];
            float am[8] = {a0.x,a0.y,a0.z,a0.w,a1.x,a1.y,a1.z,a1.w};
#pragma unroll
            for (int i = 0; i < 8; i++) {
                acc1[i].x = fmaf(am[i], c.x, acc1[i].x);
                acc1[i].y = fmaf(am[i], c.y, acc1[i].y);
                acc1[i].z = fmaf(am[i], c.z, acc1[i].z);
                acc1[i].w = fmaf(am[i], c.w, acc1[i].w);
                acc2[i].x = fmaf(am[i], d.x, acc2[i].x);
                acc2[i].y = fmaf(am[i], d.y, acc2[i].y);
                acc2[i].z = fmaf(am[i], d.z, acc2[i].z);
                acc2[i].w = fmaf(am[i], d.w, acc2[i].w);
            }
        }
        if (k0 + 1 < PNK) {
            PSTORE((k0 + 1) & 1);
            __syncthreads();
        }
    }

    // Q epilogue: rows m0+ty*8+i, cols n0+tx*4
#pragma unroll
    for (int i = 0; i < 8; i++) {
        *(float4*)&g_Q[(m0 + ty * 8 + i) * Un + n0 + tx * 4] = acc1[i];
    }
    // KT epilogue: KT[b][u][q] = K + bh; q = (m0&255)+ty*8+i, u = n0+tx*4+j
    {
        const int bidx = m0 >> 8;
        const int q0 = (m0 & 255) + ty * 8;
        const float* accf = (const float*)acc2;   // [i][j]
#pragma unroll
        for (int j = 0; j < 4; j++) {
            const int u = n0 + tx * 4 + j;
            const float bhv = __ldg(&bh[u]);
            float4 lo = make_float4(accf[0*4+j]+bhv, accf[1*4+j]+bhv,
                                    accf[2*4+j]+bhv, accf[3*4+j]+bhv);
            float4 hi = make_float4(accf[4*4+j]+bhv, accf[5*4+j]+bhv,
                                    accf[6*4+j]+bhv, accf[7*4+j]+bhv);
            *(float4*)&g_KT[(bidx * Un + u) * Ln + q0]     = lo;
            *(float4*)&g_KT[(bidx * Un + u) * Ln + q0 + 4] = hi;
        }
    }
#undef PLOAD
#undef PSTORE
}

// ---------------------------------------------------------------------------
// Kernel 2: partial scores. 1024 CTAs x 256 threads. Each CTA: one p-tile of 4
// rows x one half of U (256 u). 16 tanh per iter behind 1 LDG.128 + 1 LDS.128.
// Writes un-normalized partial e to g_E[h][b][p][q].
// ---------------------------------------------------------------------------
#define PT 4
#define UH 256      // u per CTA (half of Un)
#define USPL 4      // u sub-splits within CTA
#define UCH (UH/USPL)  // 64

__global__ __launch_bounds__(256) void escore_kernel(
    const float* __restrict__ Wv)   // [512]
{
    __shared__ float4 QsT[UH];          // [u_local] -> Q[p0..p0+3][u]   4 KB
    __shared__ float  Wvs[UH];          // 1 KB
    __shared__ float  epart[USPL * PT * Ln];  // [us][p][q]  16 KB

    const int tid = threadIdx.x;
    const int tileid = blockIdx.x >> 1;
    const int h  = blockIdx.x & 1;        // U half
    const int b  = tileid >> 6;
    const int p0 = (tileid & 63) * PT;
    const int u0g = h * UH;

    // Stage Q (transposed) and Wv for this u-range
    {
        float* qst = (float*)QsT;
#pragma unroll
        for (int i = tid; i < PT * UH; i += 256) {
            int p = i >> 8;       // 0..3
            int ul = i & 255;
            qst[ul * 4 + p] = g_Q[(b * Ln + p0 + p) * Un + u0g + ul];
        }
        Wvs[tid] = Wv[u0g + tid];
    }
    __syncthreads();

    const int us = tid >> 6;       // 0..3
    const int qg = tid & 63;       // q-group (4 wide)
    const float4* __restrict__ kt4 = (const float4*)(g_KT + (size_t)b * Un * Ln);

    float4 e0 = make_float4(0.f,0.f,0.f,0.f), e1 = e0, e2 = e0, e3 = e0;
    const int ul0 = us * UCH;
#pragma unroll 4
    for (int i = 0; i < UCH; i++) {
        const int ul = ul0 + i;
        float4 kv = __ldg(&kt4[(u0g + ul) * 64 + qg]);
        float4 q4 = QsT[ul];
        float  wv = Wvs[ul];
        e0.x = fmaf(wv, tanh_approx(q4.x + kv.x), e0.x);
        e0.y = fmaf(wv, tanh_approx(q4.x + kv.y), e0.y);
        e0.z = fmaf(wv, tanh_approx(q4.x + kv.z), e0.z);
        e0.w = fmaf(wv, tanh_approx(q4.x + kv.w), e0.w);
        e1.x = fmaf(wv, tanh_approx(q4.y + kv.x), e1.x);
        e1.y = fmaf(wv, tanh_approx(q4.y + kv.y), e1.y);
        e1.z = fmaf(wv, tanh_approx(q4.y + kv.z), e1.z);
        e1.w = fmaf(wv, tanh_approx(q4.y + kv.w), e1.w);
        e2.x = fmaf(wv, tanh_approx(q4.z + kv.x), e2.x);
        e2.y = fmaf(wv, tanh_approx(q4.z + kv.y), e2.y);
        e2.z = fmaf(wv, tanh_approx(q4.z + kv.z), e2.z);
        e2.w = fmaf(wv, tanh_approx(q4.z + kv.w), e2.w);
        e3.x = fmaf(wv, tanh_approx(q4.w + kv.x), e3.x);
        e3.y = fmaf(wv, tanh_approx(q4.w + kv.y), e3.y);
        e3.z = fmaf(wv, tanh_approx(q4.w + kv.z), e3.z);
        e3.w = fmaf(wv, tanh_approx(q4.w + kv.w), e3.w);
    }
    // ba is a uniform shift of e -> cancels exactly in the exp-normalize.

    {
        float4* ep4 = (float4*)epart;
        ep4[(us * 4 + 0) * 64 + qg] = e0;
        ep4[(us * 4 + 1) * 64 + qg] = e1;
        ep4[(us * 4 + 2) * 64 + qg] = e2;
        ep4[(us * 4 + 3) * 64 + qg] = e3;
    }
    __syncthreads();

    // Reduce 4 u-splits, write partial scores: iteration j -> p=j, q=tid
#pragma unroll
    for (int j = 0; j < PT; j++) {
        float s = epart[(0 * 4 + j) * 256 + tid]
                + epart[(1 * 4 + j) * 256 + tid]
                + epart[(2 * 4 + j) * 256 + tid]
                + epart[(3 * 4 + j) * 256 + tid];
        g_E[(((size_t)h * Bn + b) * Ln + p0 + j) * Ln + tid] = s;
    }
}

// ---------------------------------------------------------------------------
// Kernel 3: normalize + epilogue GEMM. 256 CTAs (64 p-tiles x 4 f-tiles),
// 256 threads. Tile: 32 p-rows x 128 f-cols, full q=256 reduction.
// ---------------------------------------------------------------------------
#define OPT 32    // p rows per CTA
#define OFT 128   // f cols per CTA
#define APAD 36   // aT row pitch (floats): 16B-aligned, modest bank conflicts

__global__ __launch_bounds__(256) void out_kernel(
    const float* __restrict__ X,    // [8,256,512]
    float* __restrict__ out)        // [8,256,512]
{
    __shared__ float aT[Ln * APAD];   // [q][p_local], 36 KB

    const int tid = threadIdx.x;
    const int ftile = blockIdx.x & 3;
    const int ptile = blockIdx.x >> 2;          // 0..63
    const int b = ptile >> 3;
    const int prow0 = (ptile & 7) * OPT;
    const int f0 = ftile * OFT;

    // --- normalize: warp w handles rows lr = w*4 .. w*4+3 ---
    {
        const int w = tid >> 5, l = tid & 31;
        const float* E0 = g_E + ((size_t)0 * Bn + b) * Ln * Ln;
        const float* E1 = g_E + ((size_t)1 * Bn + b) * Ln * Ln;
#pragma unroll
        for (int r = 0; r < 4; r++) {
            const int p = prow0 + w * 4 + r;
            float v[8];
            float m = -1e30f;
#pragma unroll
            for (int j = 0; j < 8; j++) {
                int q = l + j * 32;
                v[j] = E0[p * Ln + q] + E1[p * Ln + q];
                m = fmaxf(m, v[j]);
            }
#pragma unroll
            for (int o = 16; o > 0; o >>= 1)
                m = fmaxf(m, __shfl_xor_sync(0xffffffffu, m, o));
            float s = 0.f;
#pragma unroll
            for (int j = 0; j < 8; j++) {
                v[j] = __expf(v[j] - m);
                s += v[j];
            }
#pragma unroll
            for (int o = 16; o > 0; o >>= 1)
                s += __shfl_xor_sync(0xffffffffu, s, o);
            float inv = 1.f / (s + 1e-7f);
#pragma unroll
            for (int j = 0; j < 8; j++)
                aT[(l + j * 32) * APAD + w * 4 + r] = v[j] * inv;
        }
    }
    __syncthreads();

    // --- epilogue: thread = (py 0..7 -> 4 p rows, lane 0..31 -> 4 f cols) ---
    const int py = tid >> 5;
    const int lane = tid & 31;
    const float4* __restrict__ xin4 =
        (const float4*)(X + (size_t)b * Ln * Fn) + ftile * 32 + lane;

    float4 o0 = make_float4(0.f,0.f,0.f,0.f), o1 = o0, o2 = o0, o3 = o0;
#pragma unroll 4
    for (int q = 0; q < Ln; q++) {
        float4 x4 = __ldg(&xin4[q * (Fn / 4)]);
        float4 a4 = *(const float4*)&aT[q * APAD + py * 4];  // warp-broadcast
        o0.x = fmaf(a4.x, x4.x, o0.x); o0.y = fmaf(a4.x, x4.y, o0.y);
        o0.z = fmaf(a4.x, x4.z, o0.z); o0.w = fmaf(a4.x, x4.w, o0.w);
        o1.x = fmaf(a4.y, x4.x, o1.x); o1.y = fmaf(a4.y, x4.y, o1.y);
        o1.z = fmaf(a4.y, x4.z, o1.z); o1.w = fmaf(a4.y, x4.w, o1.w);
        o2.x = fmaf(a4.z, x4.x, o2.x); o2.y = fmaf(a4.z, x4.y, o2.y);
        o2.z = fmaf(a4.z, x4.z, o2.z); o2.w = fmaf(a4.z, x4.w, o2.w);
        o3.x = fmaf(a4.w, x4.x, o3.x); o3.y = fmaf(a4.w, x4.y, o3.y);
        o3.z = fmaf(a4.w, x4.z, o3.z); o3.w = fmaf(a4.w, x4.w, o3.w);
    }

    float* obase = out + ((size_t)b * Ln + prow0 + py * 4) * Fn + f0 + lane * 4;
    *(float4*)&obase[0 * Fn] = o0;
    *(float4*)&obase[1 * Fn] = o1;
    *(float4*)&obase[2 * Fn] = o2;
    *(float4*)&obase[3 * Fn] = o3;
}

extern "C" void kernel_launch(void* const* d_in, const int* in_sizes, int n_in,
                              void* d_out, int out_size) {
    const float* X  = (const float*)d_in[0];
    const float* Wq = (const float*)d_in[1];
    const float* Wk = (const float*)d_in[2];
    const float* Wv = (const float*)d_in[3];
    const float* bh = (const float*)d_in[4];
    // d_in[5] = ba: cancels exactly in the exp-normalize; unused.
    float* out = (float*)d_out;

    dim3 gridP(Un / PBN, Mn / PBM);            // (8, 32) = 256 CTAs
    proj_kernel<<<gridP, 128>>>(X, Wq, Wk, bh);

    escore_kernel<<<2 * Bn * (Ln / PT), 256>>>(Wv);   // 1024 CTAs

    out_kernel<<<(Mn / OPT) * (Fn / OFT), 256>>>(X, out);  // 256 CTAs
}

// round 6
// speedup vs baseline: 1.0258x; 1.0258x over previous
#include <cuda_runtime.h>

// Shapes (fixed): B=8, L=256, F=512, U=512.
#define Bn 8
#define Ln 256
#define Fn 512
#define Un 512
#define Mn (Bn*Ln)   // 2048

// Scratch
__device__ __align__(16) float g_Q[Mn * Un];        // [2048][512]
__device__ __align__(16) float g_KT[Bn * Un * Ln];  // [8][512][256]  K+bh, u-major
__device__ __align__(16) float g_A[Bn * Ln * Ln];   // [8][256][256]  normalized weights

__device__ __forceinline__ float tanh_approx(float x) {
    float y;
    asm("tanh.approx.f32 %0, %1;" : "=f"(y) : "f"(x));
    return y;
}

typedef unsigned long long ull;

__device__ __forceinline__ ull f2ull(float x, float y) {
    ull v;
    asm("mov.b64 %0, {%1, %2};" : "=l"(v) : "f"(x), "f"(y));
    return v;
}
__device__ __forceinline__ float2 ull2f2(ull v) {
    float2 r;
    asm("mov.b64 {%0, %1}, %2;" : "=f"(r.x), "=f"(r.y) : "l"(v));
    return r;
}
#define FMA2(d, a, b, c) \
    asm("fma.rn.f32x2 %0, %1, %2, %3;" : "=l"(d) : "l"(a), "l"(b), "l"(c))

// ---------------------------------------------------------------------------
// Kernel 1: dual SGEMM, Q = X*Wq and KT = (X*Wk + bh)^T.
// 64x64 tile, BK=16, 256 threads, 4x4 dual microtile, packed f32x2 FMA,
// double-buffered smem (one sync per k-step).
// ---------------------------------------------------------------------------
#define PBM 64
#define PBN 64
#define PBK 16
#define PNK (Fn/PBK)   // 32

__global__ __launch_bounds__(256) void proj_kernel(
    const float* __restrict__ X,    // [2048,512]
    const float* __restrict__ Wq,   // [512,512]
    const float* __restrict__ Wk,   // [512,512]
    const float* __restrict__ bh)   // [512]
{
    __shared__ float As [2][PBK][PBM];
    __shared__ float B1s[2][PBK][PBN];
    __shared__ float B2s[2][PBK][PBN];

    const int tid = threadIdx.x;
    const int tx = tid & 15;   // n direction (4 cols)
    const int ty = tid >> 4;   // m direction (4 rows)
    const int m0 = blockIdx.y * PBM;
    const int n0 = blockIdx.x * PBN;

    // acc[m][pair]: pair 0 = n-cols {0,1}, pair 1 = {2,3}
    ull c1[4][2], c2[4][2];
#pragma unroll
    for (int i = 0; i < 4; i++) {
        c1[i][0] = 0ULL; c1[i][1] = 0ULL;
        c2[i][0] = 0ULL; c2[i][1] = 0ULL;
    }

    // loaders (256 threads): A tile 64r x 16k, one float4/thread
    const int a_row = tid >> 2;
    const int a_k4  = (tid & 3) * 4;
    // B tiles 16k x 64n, one float4/thread each
    const int b_k  = tid >> 4;
    const int b_n4 = (tid & 15) * 4;

    float4 av, bq, bk;
#define PLOAD(K0)                                                      \
    do {                                                               \
        av = *(const float4*)&X [(m0 + a_row) * Fn + (K0) + a_k4];     \
        bq = *(const float4*)&Wq[((K0) + b_k) * Un + n0 + b_n4];       \
        bk = *(const float4*)&Wk[((K0) + b_k) * Un + n0 + b_n4];       \
    } while (0)
#define PSTORE(S)                                                      \
    do {                                                               \
        As[S][a_k4 + 0][a_row] = av.x;                                 \
        As[S][a_k4 + 1][a_row] = av.y;                                 \
        As[S][a_k4 + 2][a_row] = av.z;                                 \
        As[S][a_k4 + 3][a_row] = av.w;                                 \
        *(float4*)&B1s[S][b_k][b_n4] = bq;                             \
        *(float4*)&B2s[S][b_k][b_n4] = bk;                             \
    } while (0)

    PLOAD(0);
    PSTORE(0);
    __syncthreads();

    for (int k0 = 0; k0 < PNK; k0++) {
        const int s = k0 & 1;
        if (k0 + 1 < PNK) PLOAD((k0 + 1) * PBK);
#pragma unroll
        for (int kk = 0; kk < PBK; kk++) {
            float4 a4 = *(const float4*)&As[s][kk][ty * 4];
            ulonglong2 cb = *(const ulonglong2*)&B1s[s][kk][tx * 4];
            ulonglong2 db = *(const ulonglong2*)&B2s[s][kk][tx * 4];
            float am[4] = {a4.x, a4.y, a4.z, a4.w};
#pragma unroll
            for (int i = 0; i < 4; i++) {
                ull as = f2ull(am[i], am[i]);
                FMA2(c1[i][0], as, cb.x, c1[i][0]);
                FMA2(c1[i][1], as, cb.y, c1[i][1]);
                FMA2(c2[i][0], as, db.x, c2[i][0]);
                FMA2(c2[i][1], as, db.y, c2[i][1]);
            }
        }
        if (k0 + 1 < PNK) {
            PSTORE((k0 + 1) & 1);
            __syncthreads();
        }
    }

    // Q epilogue
#pragma unroll
    for (int i = 0; i < 4; i++) {
        float2 lo = ull2f2(c1[i][0]);
        float2 hi = ull2f2(c1[i][1]);
        float4 v = make_float4(lo.x, lo.y, hi.x, hi.y);
        *(float4*)&g_Q[(m0 + ty * 4 + i) * Un + n0 + tx * 4] = v;
    }
    // KT epilogue: KT[b][u][q] = K + bh (tile never spans batches: 64 | 256)
    {
        const int bidx = m0 >> 8;
        const int q0 = (m0 & 255) + ty * 4;
        float kf[4][4];
#pragma unroll
        for (int i = 0; i < 4; i++) {
            float2 lo = ull2f2(c2[i][0]);
            float2 hi = ull2f2(c2[i][1]);
            kf[i][0] = lo.x; kf[i][1] = lo.y; kf[i][2] = hi.x; kf[i][3] = hi.y;
        }
#pragma unroll
        for (int j = 0; j < 4; j++) {
            const int u = n0 + tx * 4 + j;
            const float bhv = __ldg(&bh[u]);
            float4 v = make_float4(kf[0][j] + bhv, kf[1][j] + bhv,
                                   kf[2][j] + bhv, kf[3][j] + bhv);
            *(float4*)&g_KT[(bidx * Un + u) * Ln + q0] = v;
        }
    }
#undef PLOAD
#undef PSTORE
}

// ---------------------------------------------------------------------------
// Kernel 2: additive-attention scores (MUFU-bound). 512 CTAs x 512 threads.
// Thread = (us 0..7 of 8 u-splits, qg 0..63 of 4-wide q groups); 16 tanh per
// iter behind 1 LDG.128 + 1 LDS.128. Reduce + normalize, write a to g_A.
// Shared scratch is ONE array (round-3 split-declaration bug fixed).
// ---------------------------------------------------------------------------
#define PT 4
#define USPLIT 8
#define UCH (Un/USPLIT)   // 64

__global__ __launch_bounds__(512) void attn_kernel(
    const float* __restrict__ Wv)   // [512]
{
    __shared__ float4 QsT[Un];            // [u] -> Q[p0..p0+3][u]   8 KB
    __shared__ float  Wvs[Un];            // 2 KB
    __shared__ float  ep[USPLIT * PT * Ln];  // [us][p][q] = [8][4][256]  32 KB
    __shared__ float  aT[Ln * PT];        // [q][p]  4 KB

    const int tid = threadIdx.x;
    const int b  = blockIdx.x >> 6;
    const int p0 = (blockIdx.x & 63) * PT;

    // Stage Q transposed and Wv
    {
        float* qst = (float*)QsT;
#pragma unroll
        for (int i = tid; i < PT * Un; i += 512) {
            int p = i >> 9;
            int u = i & 511;
            qst[u * 4 + p] = g_Q[(b * Ln + p0 + p) * Un + u];
        }
        Wvs[tid] = Wv[tid];
    }
    __syncthreads();

    const int us = tid >> 6;
    const int qg = tid & 63;
    const float4* __restrict__ kt4 = (const float4*)(g_KT + (size_t)b * Un * Ln);

    float4 e0 = make_float4(0.f,0.f,0.f,0.f), e1 = e0, e2 = e0, e3 = e0;
    const int u0 = us * UCH;
#pragma unroll 4
    for (int i = 0; i < UCH; i++) {
        const int u = u0 + i;
        float4 kv = __ldg(&kt4[u * 64 + qg]);
        float4 q4 = QsT[u];
        float  wv = Wvs[u];
        e0.x = fmaf(wv, tanh_approx(q4.x + kv.x), e0.x);
        e0.y = fmaf(wv, tanh_approx(q4.x + kv.y), e0.y);
        e0.z = fmaf(wv, tanh_approx(q4.x + kv.z), e0.z);
        e0.w = fmaf(wv, tanh_approx(q4.x + kv.w), e0.w);
        e1.x = fmaf(wv, tanh_approx(q4.y + kv.x), e1.x);
        e1.y = fmaf(wv, tanh_approx(q4.y + kv.y), e1.y);
        e1.z = fmaf(wv, tanh_approx(q4.y + kv.z), e1.z);
        e1.w = fmaf(wv, tanh_approx(q4.y + kv.w), e1.w);
        e2.x = fmaf(wv, tanh_approx(q4.z + kv.x), e2.x);
        e2.y = fmaf(wv, tanh_approx(q4.z + kv.y), e2.y);
        e2.z = fmaf(wv, tanh_approx(q4.z + kv.z), e2.z);
        e2.w = fmaf(wv, tanh_approx(q4.z + kv.w), e2.w);
        e3.x = fmaf(wv, tanh_approx(q4.w + kv.x), e3.x);
        e3.y = fmaf(wv, tanh_approx(q4.w + kv.y), e3.y);
        e3.z = fmaf(wv, tanh_approx(q4.w + kv.z), e3.z);
        e3.w = fmaf(wv, tanh_approx(q4.w + kv.w), e3.w);
    }
    // ba is a uniform shift of e -> cancels exactly in the exp-normalize.

    {
        float4* ep4 = (float4*)ep;
        ep4[(us * 4 + 0) * 64 + qg] = e0;
        ep4[(us * 4 + 1) * 64 + qg] = e1;
        ep4[(us * 4 + 2) * 64 + qg] = e2;
        ep4[(us * 4 + 3) * 64 + qg] = e3;
    }
    __syncthreads();

    // Reduce 8 u-split partials -> aT[q][p]
#pragma unroll
    for (int idx = tid; idx < PT * Ln; idx += 512) {
        int p = idx >> 8;
        int q = idx & 255;
        float s = 0.f;
#pragma unroll
        for (int u = 0; u < USPLIT; u++)
            s += ep[(u * 4 + p) * 256 + q];
        aT[q * 4 + p] = s;
    }
    __syncthreads();

    // Normalize rows in place: warp w handles row p = w (w < 4)
    {
        const int w = tid >> 5, l = tid & 31;
        if (w < PT) {
            float m = -1e30f;
#pragma unroll
            for (int j = 0; j < 8; j++) m = fmaxf(m, aT[(l + j * 32) * 4 + w]);
#pragma unroll
            for (int o = 16; o > 0; o >>= 1)
                m = fmaxf(m, __shfl_xor_sync(0xffffffffu, m, o));
            float ex[8];
            float s = 0.f;
#pragma unroll
            for (int j = 0; j < 8; j++) {
                ex[j] = __expf(aT[(l + j * 32) * 4 + w] - m);
                s += ex[j];
            }
#pragma unroll
            for (int o = 16; o > 0; o >>= 1)
                s += __shfl_xor_sync(0xffffffffu, s, o);
            float inv = 1.f / (s + 1e-7f);
#pragma unroll
            for (int j = 0; j < 8; j++) aT[(l + j * 32) * 4 + w] = ex[j] * inv;
        }
    }
    __syncthreads();

    // Store normalized weights: g_A[b][p0+p][q]  (coalesced over q)
#pragma unroll
    for (int idx = tid; idx < PT * Ln; idx += 512) {
        int p = idx >> 8;
        int q = idx & 255;
        g_A[((size_t)b * Ln + p0 + p) * Ln + q] = aT[q * 4 + p];
    }
}

// ---------------------------------------------------------------------------
// Kernel 3: epilogue GEMM out[p,f] = sum_q a[p][q] * X[b,q,f].
// 256 CTAs (64 p-tiles x 4 f-tiles), 256 threads; 32p x 128f tile, q=256.
// ---------------------------------------------------------------------------
#define OPT 32
#define OFT 128
#define APAD 36

__global__ __launch_bounds__(256) void out_kernel(
    const float* __restrict__ X,    // [8,256,512]
    float* __restrict__ out)        // [8,256,512]
{
    __shared__ float aT[Ln * APAD];   // [q][p_local], 36 KB

    const int tid = threadIdx.x;
    const int ftile = blockIdx.x & 3;
    const int ptile = blockIdx.x >> 2;   // 0..63
    const int b = ptile >> 3;
    const int prow0 = (ptile & 7) * OPT;
    const int f0 = ftile * OFT;

    // Load weights tile into smem (coalesced over q)
    {
        const float* asrc = g_A + ((size_t)b * Ln + prow0) * Ln;
#pragma unroll
        for (int idx = tid; idx < OPT * Ln; idx += 256) {
            int p = idx >> 8;
            int q = idx & 255;
            aT[q * APAD + p] = asrc[p * Ln + q];
        }
    }
    __syncthreads();

    // thread = (py 0..7 -> 4 p rows, lane 0..31 -> 4 f cols)
    const int py = tid >> 5;
    const int lane = tid & 31;
    const float4* __restrict__ xin4 =
        (const float4*)(X + (size_t)b * Ln * Fn) + ftile * 32 + lane;

    float4 o0 = make_float4(0.f,0.f,0.f,0.f), o1 = o0, o2 = o0, o3 = o0;
#pragma unroll 4
    for (int q = 0; q < Ln; q++) {
        float4 x4 = __ldg(&xin4[q * (Fn / 4)]);
        float4 a4 = *(const float4*)&aT[q * APAD + py * 4];  // warp-broadcast
        o0.x = fmaf(a4.x, x4.x, o0.x); o0.y = fmaf(a4.x, x4.y, o0.y);
        o0.z = fmaf(a4.x, x4.z, o0.z); o0.w = fmaf(a4.x, x4.w, o0.w);
        o1.x = fmaf(a4.y, x4.x, o1.x); o1.y = fmaf(a4.y, x4.y, o1.y);
        o1.z = fmaf(a4.y, x4.z, o1.z); o1.w = fmaf(a4.y, x4.w, o1.w);
        o2.x = fmaf(a4.z, x4.x, o2.x); o2.y = fmaf(a4.z, x4.y, o2.y);
        o2.z = fmaf(a4.z, x4.z, o2.z); o2.w = fmaf(a4.z, x4.w, o2.w);
        o3.x = fmaf(a4.w, x4.x, o3.x); o3.y = fmaf(a4.w, x4.y, o3.y);
        o3.z = fmaf(a4.w, x4.z, o3.z); o3.w = fmaf(a4.w, x4.w, o3.w);
    }

    float* obase = out + ((size_t)b * Ln + prow0 + py * 4) * Fn + f0 + lane * 4;
    *(float4*)&obase[0 * Fn] = o0;
    *(float4*)&obase[1 * Fn] = o1;
    *(float4*)&obase[2 * Fn] = o2;
    *(float4*)&obase[3 * Fn] = o3;
}

extern "C" void kernel_launch(void* const* d_in, const int* in_sizes, int n_in,
                              void* d_out, int out_size) {
    const float* X  = (const float*)d_in[0];
    const float* Wq = (const float*)d_in[1];
    const float* Wk = (const float*)d_in[2];
    const float* Wv = (const float*)d_in[3];
    const float* bh = (const float*)d_in[4];
    // d_in[5] = ba: cancels exactly in the exp-normalize; unused.
    float* out = (float*)d_out;

    dim3 gridP(Un / PBN, Mn / PBM);            // (8, 32) = 256 CTAs
    proj_kernel<<<gridP, 256>>>(X, Wq, Wk, bh);

    attn_kernel<<<Bn * (Ln / PT), 512>>>(Wv);  // 512 CTAs

    out_kernel<<<(Mn / OPT) * (Fn / OFT), 256>>>(X, out);  // 256 CTAs
}